// round 7
// baseline (speedup 1.0000x reference)
#include <cuda_runtime.h>
#include <cuda_fp16.h>

#define MAX_NODES 100000
#define MAX_EDGES 1600000
#define OUTF 64
#define INF  128
#define XT_STRIDE 68

// Scratch (no cudaMalloc allowed)
__device__ __half g_hA[MAX_NODES * OUTF];
__device__ __half g_hB[MAX_NODES * OUTF];
// deg[MAX_NODES] followed by lookback state (1024 ints = 512 ullongs); one memset.
__device__ __align__(8) int g_degstate[MAX_NODES + 1024];
__device__ int   g_row_ptr[MAX_NODES + 1];
__device__ int   g_wptr[MAX_NODES];
__device__ int2  g_csr[MAX_EDGES];          // {src, float_bits(w)} dst-CSR order

// ---------------- packed f32x2 helpers (Blackwell FFMA2) --------------------
__device__ __forceinline__ unsigned long long pk2(float lo, float hi) {
    unsigned long long r;
    asm("mov.b64 %0, {%1,%2};" : "=l"(r) : "f"(lo), "f"(hi));
    return r;
}
__device__ __forceinline__ void upk2(float& lo, float& hi, unsigned long long v) {
    asm("mov.b64 {%0,%1}, %2;" : "=f"(lo), "=f"(hi) : "l"(v));
}
__device__ __forceinline__ void fma2(unsigned long long& d,
                                     unsigned long long a, unsigned long long b) {
    asm("fma.rn.f32x2 %0, %1, %2, %0;" : "+l"(d) : "l"(a), "l"(b));
}

// ---------------------------------------------------------------------------
// Decode edge_index (auto int32/int64) and count per-dst degrees. No src/dst
// materialization — scatter re-decodes.
// ---------------------------------------------------------------------------
__device__ __forceinline__ bool detect_is64(const int* raw) {
    bool is64 = true;
#pragma unroll
    for (int i = 1; i < 64; i += 2)
        if (raw[i] != 0) is64 = false;
    return is64;
}

__global__ void count_kernel(const int* __restrict__ raw, int E,
                             int* __restrict__ deg)
{
    bool is64 = detect_is64(raw);
    int e = blockIdx.x * blockDim.x + threadIdx.x;
    if (e >= E) return;
    int d = is64 ? raw[2 * E + 2 * e] : raw[E + e];
    atomicAdd(&deg[d], 1);
}

// ---------------------------------------------------------------------------
// Single-launch exclusive scan with decoupled lookback.
// state[b]: bits[1:0] flag (0=invalid, 1=aggregate, 2=inclusive), bits[63:2] sum.
// 391 blocks, 256 threads — fits in one wave; lookback cannot deadlock.
// ---------------------------------------------------------------------------
__global__ void scan_lookback_kernel(const int* __restrict__ deg,
                                     unsigned long long* __restrict__ state,
                                     int* __restrict__ row_ptr,
                                     int* __restrict__ wptr, int n, int E)
{
    __shared__ int wsum[8];
    __shared__ int s_excl;
    const int b = blockIdx.x;
    const int i = b * 256 + threadIdx.x;
    const int lane = threadIdx.x & 31, wid = threadIdx.x >> 5;
    int v = (i < n) ? deg[i] : 0;

    int s = v;
#pragma unroll
    for (int o = 1; o < 32; o <<= 1) {
        int t = __shfl_up_sync(0xffffffffu, s, o);
        if (lane >= o) s += t;
    }
    if (lane == 31) wsum[wid] = s;
    __syncthreads();
    if (wid == 0 && lane < 8) {
        int ws = wsum[lane];
#pragma unroll
        for (int o = 1; o < 8; o <<= 1) {
            int t = __shfl_up_sync(0x000000ffu, ws, o);
            if (lane >= o) ws += t;
        }
        wsum[lane] = ws;
    }
    __syncthreads();

    if (threadIdx.x == 0) {
        int agg = wsum[7];
        if (b == 0) {
            atomicExch(&state[0], ((unsigned long long)agg << 2) | 2ull);
            s_excl = 0;
        } else {
            atomicExch(&state[b], ((unsigned long long)agg << 2) | 1ull);
            int excl = 0;
            for (int j = b - 1;; j--) {
                unsigned long long st;
                do { st = *(volatile unsigned long long*)&state[j]; }
                while (!(st & 3ull));
                excl += (int)(st >> 2);
                if ((st & 3ull) == 2ull) break;
            }
            atomicExch(&state[b], ((unsigned long long)(excl + agg) << 2) | 2ull);
            s_excl = excl;
        }
    }
    __syncthreads();

    int excl_elem = s_excl + (s - v) + (wid ? wsum[wid - 1] : 0);
    if (i < n) { row_ptr[i] = excl_elem; wptr[i] = excl_elem; }
    if (i == 0) row_ptr[n] = E;
}

// ---------------------------------------------------------------------------
__global__ void scatter_kernel(const int* __restrict__ raw,
                               const float* __restrict__ w,
                               int* __restrict__ wptr,
                               int2* __restrict__ csr, int E)
{
    bool is64 = detect_is64(raw);
    int e = blockIdx.x * blockDim.x + threadIdx.x;
    if (e >= E) return;
    int s, d;
    if (is64) { s = raw[2 * e]; d = raw[2 * E + 2 * e]; }
    else      { s = raw[e];     d = raw[E + e]; }
    int pos = atomicAdd(&wptr[d], 1);
    csr[pos] = make_int2(s, __float_as_int(w[e]));
}

// ---------------------------------------------------------------------------
// GEMM, node-packed f32x2: h0 = fp16(x @ W^T + b). 64x64 tile, 256 threads.
// ---------------------------------------------------------------------------
__global__ void gemm_kernel(const float* __restrict__ x,
                            const float* __restrict__ W,
                            const float* __restrict__ bias,
                            __half* __restrict__ out, int n)
{
    extern __shared__ float sm[];
    float* xsT = sm;                          // [128 k][XT_STRIDE] node-inner
    float* ws  = sm + INF * XT_STRIDE;        // [128 k][XT_STRIDE] col-inner

    const int tid = threadIdx.x;
    const int n_base = blockIdx.x * 64;

    for (int i = tid; i < OUTF * INF; i += 256) {
        int c = i >> 7;
        int k = i & 127;
        ws[k * XT_STRIDE + c] = W[i];
    }
    {
        int node = tid & 63;
        int kb = (tid >> 6) * 32;
        int gn = n_base + node;
#pragma unroll
        for (int j = 0; j < 8; j++) {
            int k = kb + j * 4;
            float4 v = make_float4(0.f, 0.f, 0.f, 0.f);
            if (gn < n) v = *(const float4*)(x + (size_t)gn * INF + k);
            xsT[(k + 0) * XT_STRIDE + node] = v.x;
            xsT[(k + 1) * XT_STRIDE + node] = v.y;
            xsT[(k + 2) * XT_STRIDE + node] = v.z;
            xsT[(k + 3) * XT_STRIDE + node] = v.w;
        }
    }
    __syncthreads();

    const int c0 = (tid & 15) * 4;
    const int n0 = (tid >> 4) * 4;

    unsigned long long acc[2][4];
#pragma unroll
    for (int p = 0; p < 2; p++)
#pragma unroll
        for (int j = 0; j < 4; j++) acc[p][j] = 0ull;

#pragma unroll 4
    for (int k = 0; k < INF; k++) {
        ulonglong2 xp = *(const ulonglong2*)(xsT + k * XT_STRIDE + n0);
        float4 wv = *(const float4*)(ws + k * XT_STRIDE + c0);
        unsigned long long w0 = pk2(wv.x, wv.x);
        unsigned long long w1 = pk2(wv.y, wv.y);
        unsigned long long w2 = pk2(wv.z, wv.z);
        unsigned long long w3 = pk2(wv.w, wv.w);
        fma2(acc[0][0], xp.x, w0); fma2(acc[0][1], xp.x, w1);
        fma2(acc[0][2], xp.x, w2); fma2(acc[0][3], xp.x, w3);
        fma2(acc[1][0], xp.y, w0); fma2(acc[1][1], xp.y, w1);
        fma2(acc[1][2], xp.y, w2); fma2(acc[1][3], xp.y, w3);
    }

    float b0 = bias[c0], b1 = bias[c0 + 1], b2 = bias[c0 + 2], b3 = bias[c0 + 3];
#pragma unroll
    for (int p = 0; p < 2; p++) {
        float lo[4], hi[4];
#pragma unroll
        for (int j = 0; j < 4; j++) upk2(lo[j], hi[j], acc[p][j]);
        int na = n_base + n0 + 2 * p;
        if (na < n) {
            __half2 h01 = __floats2half2_rn(lo[0] + b0, lo[1] + b1);
            __half2 h23 = __floats2half2_rn(lo[2] + b2, lo[3] + b3);
            *(__half2*)(out + (size_t)na * OUTF + c0)     = h01;
            *(__half2*)(out + (size_t)na * OUTF + c0 + 2) = h23;
        }
        int nb_ = na + 1;
        if (nb_ < n) {
            __half2 h01 = __floats2half2_rn(hi[0] + b0, hi[1] + b1);
            __half2 h23 = __floats2half2_rn(hi[2] + b2, hi[3] + b3);
            *(__half2*)(out + (size_t)nb_ * OUTF + c0)     = h01;
            *(__half2*)(out + (size_t)nb_ * OUTF + c0 + 2) = h23;
        }
    }
}

// ---------------------------------------------------------------------------
// CSR SpMM hop, warp-per-node. Lane = (g, q): g = edge subgroup (0..3),
// q = column quad (0..7, 8 halves = 16B each). Subgroup g processes edges
// beg+g, beg+g+4, ... ; 2 shfl_xor rounds reduce subgroups; g==0 stores.
// fp16 gather / fp32 accumulate; OUT_HALF selects output precision.
// ---------------------------------------------------------------------------
template <bool OUT_HALF>
__global__ void spmm_csr_kernel(const int* __restrict__ row_ptr,
                                const int2* __restrict__ csr,
                                const __half* __restrict__ hin,
                                void* __restrict__ hout, int n)
{
    int v = (blockIdx.x * blockDim.x + threadIdx.x) >> 5;
    if (v >= n) return;
    const int lane = threadIdx.x & 31;
    const int g = lane >> 3;
    const int q = lane & 7;

    int beg = __ldg(&row_ptr[v]);
    int end = __ldg(&row_ptr[v + 1]);

    float a[8];
#pragma unroll
    for (int j = 0; j < 8; j++) a[j] = 0.f;

    int i = beg + g;
    for (; i + 4 < end; i += 8) {
        int2 e0 = __ldg(&csr[i]);
        int2 e1 = __ldg(&csr[i + 4]);
        uint4 r0 = *(const uint4*)(hin + (size_t)e0.x * OUTF + q * 8);
        uint4 r1 = *(const uint4*)(hin + (size_t)e1.x * OUTF + q * 8);
        float w0 = __int_as_float(e0.y);
        float w1 = __int_as_float(e1.y);
        const unsigned* u0 = &r0.x;
        const unsigned* u1 = &r1.x;
#pragma unroll
        for (int j = 0; j < 4; j++) {
            float2 f0 = __half22float2(*(const __half2*)&u0[j]);
            float2 f1 = __half22float2(*(const __half2*)&u1[j]);
            a[2 * j + 0] = fmaf(w0, f0.x, a[2 * j + 0]);
            a[2 * j + 1] = fmaf(w0, f0.y, a[2 * j + 1]);
            a[2 * j + 0] = fmaf(w1, f1.x, a[2 * j + 0]);
            a[2 * j + 1] = fmaf(w1, f1.y, a[2 * j + 1]);
        }
    }
    if (i < end) {
        int2 e0 = __ldg(&csr[i]);
        uint4 r0 = *(const uint4*)(hin + (size_t)e0.x * OUTF + q * 8);
        float w0 = __int_as_float(e0.y);
        const unsigned* u0 = &r0.x;
#pragma unroll
        for (int j = 0; j < 4; j++) {
            float2 f0 = __half22float2(*(const __half2*)&u0[j]);
            a[2 * j + 0] = fmaf(w0, f0.x, a[2 * j + 0]);
            a[2 * j + 1] = fmaf(w0, f0.y, a[2 * j + 1]);
        }
    }

    // reduce the 4 edge subgroups (lanes q, q+8, q+16, q+24)
#pragma unroll
    for (int j = 0; j < 8; j++) {
        a[j] += __shfl_xor_sync(0xffffffffu, a[j], 8);
        a[j] += __shfl_xor_sync(0xffffffffu, a[j], 16);
    }

    if (g == 0) {
        if (OUT_HALF) {
            uint4 o;
            unsigned* ou = &o.x;
#pragma unroll
            for (int j = 0; j < 4; j++) {
                __half2 h = __floats2half2_rn(a[2 * j], a[2 * j + 1]);
                ou[j] = *(const unsigned*)&h;
            }
            *(uint4*)((__half*)hout + (size_t)v * OUTF + q * 8) = o;
        } else {
            float* fo = (float*)hout + (size_t)v * OUTF + q * 8;
            *(float4*)(fo)     = make_float4(a[0], a[1], a[2], a[3]);
            *(float4*)(fo + 4) = make_float4(a[4], a[5], a[6], a[7]);
        }
    }
}

// ---------------------------------------------------------------------------
extern "C" void kernel_launch(void* const* d_in, const int* in_sizes, int n_in,
                              void* d_out, int out_size)
{
    const float* x  = (const float*)d_in[0];
    const int*   ei = (const int*)d_in[1];
    const float* ew = (const float*)d_in[2];
    const float* Ww = (const float*)d_in[3];
    const float* Wb = (const float*)d_in[4];
    float* out = (float*)d_out;

    int n = in_sizes[0] / INF;     // 100000
    int E = in_sizes[2];           // 1600000

    __half *pA, *pB;
    int *pDegState, *pRow, *pW;
    int2 *pCsr;
    cudaGetSymbolAddress((void**)&pA, g_hA);
    cudaGetSymbolAddress((void**)&pB, g_hB);
    cudaGetSymbolAddress((void**)&pDegState, g_degstate);
    cudaGetSymbolAddress((void**)&pRow, g_row_ptr);
    cudaGetSymbolAddress((void**)&pW, g_wptr);
    cudaGetSymbolAddress((void**)&pCsr, g_csr);

    int* pDeg = pDegState;
    unsigned long long* pState = (unsigned long long*)(pDegState + MAX_NODES);

    const int GEMM_SMEM = 2 * INF * XT_STRIDE * (int)sizeof(float);
    cudaFuncSetAttribute(gemm_kernel, cudaFuncAttributeMaxDynamicSharedMemorySize,
                         GEMM_SMEM);

    int nb = (n + 255) / 256;      // 391 scan blocks

    // 1: zero deg + lookback state in one memset
    cudaMemsetAsync(pDegState, 0, ((size_t)n + 1024) * sizeof(int));
    // 2: count degrees
    count_kernel<<<(E + 255) / 256, 256>>>(ei, E, pDeg);
    // 3: single-launch exclusive scan (decoupled lookback)
    scan_lookback_kernel<<<nb, 256>>>(pDeg, pState, pRow, pW, n, E);
    // 4: scatter edges into CSR (re-decodes raw edge_index)
    scatter_kernel<<<(E + 255) / 256, 256>>>(ei, ew, pW, pCsr, E);
    // 5: h0 = fp16(x @ W^T + b)
    gemm_kernel<<<(n + 63) / 64, 256, GEMM_SMEM>>>(x, Ww, Wb, pA, n);

    // 6-8: propagation hops (warp per node). Launch #6 is what ncu profiles.
    int hop_blocks = (n * 32 + 255) / 256;
    spmm_csr_kernel<true ><<<hop_blocks, 256>>>(pRow, pCsr, pA, pB, n);
    spmm_csr_kernel<true ><<<hop_blocks, 256>>>(pRow, pCsr, pB, pA, n);
    spmm_csr_kernel<false><<<hop_blocks, 256>>>(pRow, pCsr, pA, out, n);
}

// round 8
// speedup vs baseline: 1.3226x; 1.3226x over previous
#include <cuda_runtime.h>
#include <cuda_fp16.h>

#define MAX_NODES 100000
#define MAX_EDGES 1600000
#define OUTF 64
#define INF  128
#define XS_STR 136   // half stride for HMMA smem tiles (conflict-free ldmatrix)

// Scratch (no cudaMalloc allowed)
__device__ __half g_hA[MAX_NODES * OUTF];
__device__ __half g_hB[MAX_NODES * OUTF];
__device__ __align__(8) int g_degstate[MAX_NODES + 1024]; // deg + lookback state
__device__ int   g_row_ptr[MAX_NODES + 1];
__device__ int   g_wptr[MAX_NODES];
__device__ int2  g_csr[MAX_EDGES];          // {src, float_bits(w)} dst-CSR order

// ---------------------------------------------------------------------------
__device__ __forceinline__ bool detect_is64(const int* raw) {
    bool is64 = true;
#pragma unroll
    for (int i = 1; i < 64; i += 2)
        if (raw[i] != 0) is64 = false;
    return is64;
}

__global__ void count_kernel(const int* __restrict__ raw, int E,
                             int* __restrict__ deg)
{
    bool is64 = detect_is64(raw);
    int e = blockIdx.x * blockDim.x + threadIdx.x;
    if (e >= E) return;
    int d = is64 ? raw[2 * E + 2 * e] : raw[E + e];
    atomicAdd(&deg[d], 1);
}

// ---------------------------------------------------------------------------
// Single-launch exclusive scan with decoupled lookback (391 blocks, one wave).
// ---------------------------------------------------------------------------
__global__ void scan_lookback_kernel(const int* __restrict__ deg,
                                     unsigned long long* __restrict__ state,
                                     int* __restrict__ row_ptr,
                                     int* __restrict__ wptr, int n, int E)
{
    __shared__ int wsum[8];
    __shared__ int s_excl;
    const int b = blockIdx.x;
    const int i = b * 256 + threadIdx.x;
    const int lane = threadIdx.x & 31, wid = threadIdx.x >> 5;
    int v = (i < n) ? deg[i] : 0;

    int s = v;
#pragma unroll
    for (int o = 1; o < 32; o <<= 1) {
        int t = __shfl_up_sync(0xffffffffu, s, o);
        if (lane >= o) s += t;
    }
    if (lane == 31) wsum[wid] = s;
    __syncthreads();
    if (wid == 0 && lane < 8) {
        int ws = wsum[lane];
#pragma unroll
        for (int o = 1; o < 8; o <<= 1) {
            int t = __shfl_up_sync(0x000000ffu, ws, o);
            if (lane >= o) ws += t;
        }
        wsum[lane] = ws;
    }
    __syncthreads();

    if (threadIdx.x == 0) {
        int agg = wsum[7];
        if (b == 0) {
            atomicExch(&state[0], ((unsigned long long)agg << 2) | 2ull);
            s_excl = 0;
        } else {
            atomicExch(&state[b], ((unsigned long long)agg << 2) | 1ull);
            int excl = 0;
            for (int j = b - 1;; j--) {
                unsigned long long st;
                do { st = *(volatile unsigned long long*)&state[j]; }
                while (!(st & 3ull));
                excl += (int)(st >> 2);
                if ((st & 3ull) == 2ull) break;
            }
            atomicExch(&state[b], ((unsigned long long)(excl + agg) << 2) | 2ull);
            s_excl = excl;
        }
    }
    __syncthreads();

    int excl_elem = s_excl + (s - v) + (wid ? wsum[wid - 1] : 0);
    if (i < n) { row_ptr[i] = excl_elem; wptr[i] = excl_elem; }
    if (i == 0) row_ptr[n] = E;
}

// ---------------------------------------------------------------------------
__global__ void scatter_kernel(const int* __restrict__ raw,
                               const float* __restrict__ w,
                               int* __restrict__ wptr,
                               int2* __restrict__ csr, int E)
{
    bool is64 = detect_is64(raw);
    int e = blockIdx.x * blockDim.x + threadIdx.x;
    if (e >= E) return;
    int s, d;
    if (is64) { s = raw[2 * e]; d = raw[2 * E + 2 * e]; }
    else      { s = raw[e];     d = raw[E + e]; }
    int pos = atomicAdd(&wptr[d], 1);
    csr[pos] = make_int2(s, __float_as_int(w[e]));
}

// ---------------------------------------------------------------------------
// Tensor-core GEMM (HMMA m16n8k16): h0 = fp16(x @ W^T + b).
// 128 nodes x 64 cols per block, 256 threads (8 warps), warp = 16 nodes x 64.
// x, W converted to fp16 in smem; ldmatrix-fed; fp32 accumulators.
// ---------------------------------------------------------------------------
__global__ void gemm_hmma_kernel(const float* __restrict__ x,
                                 const float* __restrict__ W,
                                 const float* __restrict__ bias,
                                 __half* __restrict__ out, int n)
{
    extern __shared__ __half smh[];
    __half* xs = smh;                        // [128][XS_STR]
    __half* ws = smh + 128 * XS_STR;         // [64][XS_STR]

    const int tid = threadIdx.x;
    const int nbase = blockIdx.x * 128;

    // W -> fp16 smem
    for (int i = tid * 4; i < OUTF * INF; i += 256 * 4) {
        int c = i >> 7, k = i & 127;
        float4 v = *(const float4*)(W + i);
        *(__half2*)(ws + c * XS_STR + k)     = __floats2half2_rn(v.x, v.y);
        *(__half2*)(ws + c * XS_STR + k + 2) = __floats2half2_rn(v.z, v.w);
    }
    // x -> fp16 smem (zero-pad tail nodes)
    for (int i = tid * 4; i < 128 * INF; i += 256 * 4) {
        int r = i >> 7, k = i & 127;
        int gn = nbase + r;
        float4 v = make_float4(0.f, 0.f, 0.f, 0.f);
        if (gn < n) v = *(const float4*)(x + (size_t)gn * INF + k);
        *(__half2*)(xs + r * XS_STR + k)     = __floats2half2_rn(v.x, v.y);
        *(__half2*)(xs + r * XS_STR + k + 2) = __floats2half2_rn(v.z, v.w);
    }
    __syncthreads();

    const int w = tid >> 5, lane = tid & 31;
    const int g = lane >> 2, tg = lane & 3;

    // A fragments for all 8 k-tiles (16 nodes x 128 k)
    unsigned af[8][4];
    {
        int r = w * 16 + (lane & 15);
        int kof = (lane >> 4) * 8;
#pragma unroll
        for (int kt = 0; kt < 8; kt++) {
            unsigned addr = (unsigned)__cvta_generic_to_shared(
                xs + r * XS_STR + kt * 16 + kof);
            asm volatile(
                "ldmatrix.sync.aligned.m8n8.x4.shared.b16 {%0,%1,%2,%3}, [%4];"
                : "=r"(af[kt][0]), "=r"(af[kt][1]), "=r"(af[kt][2]), "=r"(af[kt][3])
                : "r"(addr));
        }
    }

#pragma unroll
    for (int nt = 0; nt < 8; nt++) {
        float c0 = 0.f, c1 = 0.f, c2 = 0.f, c3 = 0.f;
        int brow = nt * 8 + (lane & 7);
        int bk = ((lane >> 3) & 1) * 8;
#pragma unroll
        for (int kt = 0; kt < 8; kt++) {
            unsigned b0, b1;
            unsigned baddr = (unsigned)__cvta_generic_to_shared(
                ws + brow * XS_STR + kt * 16 + bk);
            asm volatile(
                "ldmatrix.sync.aligned.m8n8.x2.shared.b16 {%0,%1}, [%2];"
                : "=r"(b0), "=r"(b1) : "r"(baddr));
            asm volatile(
                "mma.sync.aligned.m16n8k16.row.col.f32.f16.f16.f32 "
                "{%0,%1,%2,%3}, {%4,%5,%6,%7}, {%8,%9}, {%0,%1,%2,%3};"
                : "+f"(c0), "+f"(c1), "+f"(c2), "+f"(c3)
                : "r"(af[kt][0]), "r"(af[kt][1]), "r"(af[kt][2]), "r"(af[kt][3]),
                  "r"(b0), "r"(b1));
        }
        int col = nt * 8 + tg * 2;
        float2 bv = *(const float2*)(bias + col);
        int n0g = nbase + w * 16 + g;
        if (n0g < n)
            *(__half2*)(out + (size_t)n0g * OUTF + col) =
                __floats2half2_rn(c0 + bv.x, c1 + bv.y);
        int n1g = n0g + 8;
        if (n1g < n)
            *(__half2*)(out + (size_t)n1g * OUTF + col) =
                __floats2half2_rn(c2 + bv.x, c3 + bv.y);
    }
}

// ---------------------------------------------------------------------------
// CSR SpMM hop (R6 shape): 8 lanes/node, 8 cols each, unroll-2 edge loop.
// fp16 gather / fp32 accumulate; OUT_HALF selects output precision.
// ---------------------------------------------------------------------------
template <bool OUT_HALF>
__global__ void spmm_csr_kernel(const int* __restrict__ row_ptr,
                                const int2* __restrict__ csr,
                                const __half* __restrict__ hin,
                                void* __restrict__ hout, int n)
{
    int t = blockIdx.x * blockDim.x + threadIdx.x;
    int v = t >> 3;
    if (v >= n) return;
    int q = (threadIdx.x & 7) * 8;   // column offset (halves)

    int beg = __ldg(&row_ptr[v]);
    int end = __ldg(&row_ptr[v + 1]);

    float a[8];
#pragma unroll
    for (int j = 0; j < 8; j++) a[j] = 0.f;

    int i = beg;
    for (; i + 2 <= end; i += 2) {
        int2 e0 = __ldg(&csr[i]);
        int2 e1 = __ldg(&csr[i + 1]);
        uint4 r0 = *(const uint4*)(hin + (size_t)e0.x * OUTF + q);
        uint4 r1 = *(const uint4*)(hin + (size_t)e1.x * OUTF + q);
        float w0 = __int_as_float(e0.y);
        float w1 = __int_as_float(e1.y);
        const unsigned* u0 = &r0.x;
        const unsigned* u1 = &r1.x;
#pragma unroll
        for (int j = 0; j < 4; j++) {
            float2 f0 = __half22float2(*(const __half2*)&u0[j]);
            float2 f1 = __half22float2(*(const __half2*)&u1[j]);
            a[2 * j + 0] = fmaf(w0, f0.x, a[2 * j + 0]);
            a[2 * j + 1] = fmaf(w0, f0.y, a[2 * j + 1]);
            a[2 * j + 0] = fmaf(w1, f1.x, a[2 * j + 0]);
            a[2 * j + 1] = fmaf(w1, f1.y, a[2 * j + 1]);
        }
    }
    if (i < end) {
        int2 e0 = __ldg(&csr[i]);
        uint4 r0 = *(const uint4*)(hin + (size_t)e0.x * OUTF + q);
        float w0 = __int_as_float(e0.y);
        const unsigned* u0 = &r0.x;
#pragma unroll
        for (int j = 0; j < 4; j++) {
            float2 f0 = __half22float2(*(const __half2*)&u0[j]);
            a[2 * j + 0] = fmaf(w0, f0.x, a[2 * j + 0]);
            a[2 * j + 1] = fmaf(w0, f0.y, a[2 * j + 1]);
        }
    }

    if (OUT_HALF) {
        uint4 o;
        unsigned* ou = &o.x;
#pragma unroll
        for (int j = 0; j < 4; j++) {
            __half2 h = __floats2half2_rn(a[2 * j], a[2 * j + 1]);
            ou[j] = *(const unsigned*)&h;
        }
        *(uint4*)((__half*)hout + (size_t)v * OUTF + q) = o;
    } else {
        float* fo = (float*)hout + (size_t)v * OUTF + q;
        *(float4*)(fo)     = make_float4(a[0], a[1], a[2], a[3]);
        *(float4*)(fo + 4) = make_float4(a[4], a[5], a[6], a[7]);
    }
}

// ---------------------------------------------------------------------------
extern "C" void kernel_launch(void* const* d_in, const int* in_sizes, int n_in,
                              void* d_out, int out_size)
{
    const float* x  = (const float*)d_in[0];
    const int*   ei = (const int*)d_in[1];
    const float* ew = (const float*)d_in[2];
    const float* Ww = (const float*)d_in[3];
    const float* Wb = (const float*)d_in[4];
    float* out = (float*)d_out;

    int n = in_sizes[0] / INF;     // 100000
    int E = in_sizes[2];           // 1600000

    __half *pA, *pB;
    int *pDegState, *pRow, *pW;
    int2 *pCsr;
    cudaGetSymbolAddress((void**)&pA, g_hA);
    cudaGetSymbolAddress((void**)&pB, g_hB);
    cudaGetSymbolAddress((void**)&pDegState, g_degstate);
    cudaGetSymbolAddress((void**)&pRow, g_row_ptr);
    cudaGetSymbolAddress((void**)&pW, g_wptr);
    cudaGetSymbolAddress((void**)&pCsr, g_csr);

    int* pDeg = pDegState;
    unsigned long long* pState = (unsigned long long*)(pDegState + MAX_NODES);

    const int GEMM_SMEM = (128 + 64) * XS_STR * (int)sizeof(__half);  // 52224 B
    cudaFuncSetAttribute(gemm_hmma_kernel,
                         cudaFuncAttributeMaxDynamicSharedMemorySize, GEMM_SMEM);

    int nb = (n + 255) / 256;

    // 1: zero deg + lookback state
    cudaMemsetAsync(pDegState, 0, ((size_t)n + 1024) * sizeof(int));
    // 2: degree count
    count_kernel<<<(E + 255) / 256, 256>>>(ei, E, pDeg);
    // 3: exclusive scan (single launch)
    scan_lookback_kernel<<<nb, 256>>>(pDeg, pState, pRow, pW, n, E);
    // 4: scatter edges into CSR
    scatter_kernel<<<(E + 255) / 256, 256>>>(ei, ew, pW, pCsr, E);
    // 5: h0 = fp16(x @ W^T + b)  [tensor cores; ncu capture slot]
    gemm_hmma_kernel<<<(n + 127) / 128, 256, GEMM_SMEM>>>(x, Ww, Wb, pA, n);

    // 6-8: propagation hops
    int hop_blocks = (n * 8 + 255) / 256;
    spmm_csr_kernel<true ><<<hop_blocks, 256>>>(pRow, pCsr, pA, pB, n);
    spmm_csr_kernel<true ><<<hop_blocks, 256>>>(pRow, pCsr, pB, pA, n);
    spmm_csr_kernel<false><<<hop_blocks, 256>>>(pRow, pCsr, pA, out, n);
}

// round 9
// speedup vs baseline: 1.3500x; 1.0207x over previous
#include <cuda_runtime.h>
#include <cuda_fp16.h>

#define MAX_NODES 100000
#define MAX_EDGES 1600000
#define OUTF 64
#define INF  128
#define XS_STR 136   // half stride for HMMA smem tiles (conflict-free ldmatrix)

// Scratch (no cudaMalloc allowed)
__device__ __half g_hA[MAX_NODES * OUTF];
__device__ __half g_hB[MAX_NODES * OUTF];
__device__ __align__(8) int g_degstate[MAX_NODES + 1024]; // deg + lookback state
__device__ int   g_row_ptr[MAX_NODES + 1];
__device__ int   g_wptr[MAX_NODES];
__device__ int2  g_csr[MAX_EDGES];          // {src, float_bits(w)} dst-CSR order

// ---------------------------------------------------------------------------
__device__ __forceinline__ bool detect_is64(const int* raw) {
    bool is64 = true;
#pragma unroll
    for (int i = 1; i < 64; i += 2)
        if (raw[i] != 0) is64 = false;
    return is64;
}

__global__ void count_kernel(const int* __restrict__ raw, int E,
                             int* __restrict__ deg)
{
    bool is64 = detect_is64(raw);
    int e = blockIdx.x * blockDim.x + threadIdx.x;
    if (e >= E) return;
    int d = is64 ? raw[2 * E + 2 * e] : raw[E + e];
    atomicAdd(&deg[d], 1);
}

// ---------------------------------------------------------------------------
// Single-launch exclusive scan with decoupled lookback (391 blocks, one wave).
// ---------------------------------------------------------------------------
__global__ void scan_lookback_kernel(const int* __restrict__ deg,
                                     unsigned long long* __restrict__ state,
                                     int* __restrict__ row_ptr,
                                     int* __restrict__ wptr, int n, int E)
{
    __shared__ int wsum[8];
    __shared__ int s_excl;
    const int b = blockIdx.x;
    const int i = b * 256 + threadIdx.x;
    const int lane = threadIdx.x & 31, wid = threadIdx.x >> 5;
    int v = (i < n) ? deg[i] : 0;

    int s = v;
#pragma unroll
    for (int o = 1; o < 32; o <<= 1) {
        int t = __shfl_up_sync(0xffffffffu, s, o);
        if (lane >= o) s += t;
    }
    if (lane == 31) wsum[wid] = s;
    __syncthreads();
    if (wid == 0 && lane < 8) {
        int ws = wsum[lane];
#pragma unroll
        for (int o = 1; o < 8; o <<= 1) {
            int t = __shfl_up_sync(0x000000ffu, ws, o);
            if (lane >= o) ws += t;
        }
        wsum[lane] = ws;
    }
    __syncthreads();

    if (threadIdx.x == 0) {
        int agg = wsum[7];
        if (b == 0) {
            atomicExch(&state[0], ((unsigned long long)agg << 2) | 2ull);
            s_excl = 0;
        } else {
            atomicExch(&state[b], ((unsigned long long)agg << 2) | 1ull);
            int excl = 0;
            for (int j = b - 1;; j--) {
                unsigned long long st;
                do { st = *(volatile unsigned long long*)&state[j]; }
                while (!(st & 3ull));
                excl += (int)(st >> 2);
                if ((st & 3ull) == 2ull) break;
            }
            atomicExch(&state[b], ((unsigned long long)(excl + agg) << 2) | 2ull);
            s_excl = excl;
        }
    }
    __syncthreads();

    int excl_elem = s_excl + (s - v) + (wid ? wsum[wid - 1] : 0);
    if (i < n) { row_ptr[i] = excl_elem; wptr[i] = excl_elem; }
    if (i == 0) row_ptr[n] = E;
}

// ---------------------------------------------------------------------------
__global__ void scatter_kernel(const int* __restrict__ raw,
                               const float* __restrict__ w,
                               int* __restrict__ wptr,
                               int2* __restrict__ csr, int E)
{
    bool is64 = detect_is64(raw);
    int e = blockIdx.x * blockDim.x + threadIdx.x;
    if (e >= E) return;
    int s, d;
    if (is64) { s = raw[2 * e]; d = raw[2 * E + 2 * e]; }
    else      { s = raw[e];     d = raw[E + e]; }
    int pos = atomicAdd(&wptr[d], 1);
    csr[pos] = make_int2(s, __float_as_int(w[e]));
}

// ---------------------------------------------------------------------------
// Tensor-core GEMM (HMMA m16n8k16): h0 = fp16(x @ W^T + b).
// ALSO zeros deg + lookback state in its prologue (runs first in the graph,
// independent of the CSR build; lets hop1 sit at graph node #5 for ncu).
// ---------------------------------------------------------------------------
__global__ void gemm_hmma_kernel(const float* __restrict__ x,
                                 const float* __restrict__ W,
                                 const float* __restrict__ bias,
                                 __half* __restrict__ out,
                                 int* __restrict__ degstate, int n)
{
    // zero deg + state (MAX_NODES + 1024 ints) strided across the whole grid
    for (int i = blockIdx.x * blockDim.x + threadIdx.x;
         i < MAX_NODES + 1024; i += gridDim.x * blockDim.x)
        degstate[i] = 0;

    extern __shared__ __half smh[];
    __half* xs = smh;                        // [128][XS_STR]
    __half* ws = smh + 128 * XS_STR;         // [64][XS_STR]

    const int tid = threadIdx.x;
    const int nbase = blockIdx.x * 128;

    for (int i = tid * 4; i < OUTF * INF; i += 256 * 4) {
        int c = i >> 7, k = i & 127;
        float4 v = *(const float4*)(W + i);
        *(__half2*)(ws + c * XS_STR + k)     = __floats2half2_rn(v.x, v.y);
        *(__half2*)(ws + c * XS_STR + k + 2) = __floats2half2_rn(v.z, v.w);
    }
    for (int i = tid * 4; i < 128 * INF; i += 256 * 4) {
        int r = i >> 7, k = i & 127;
        int gn = nbase + r;
        float4 v = make_float4(0.f, 0.f, 0.f, 0.f);
        if (gn < n) v = *(const float4*)(x + (size_t)gn * INF + k);
        *(__half2*)(xs + r * XS_STR + k)     = __floats2half2_rn(v.x, v.y);
        *(__half2*)(xs + r * XS_STR + k + 2) = __floats2half2_rn(v.z, v.w);
    }
    __syncthreads();

    const int w = tid >> 5, lane = tid & 31;
    const int g = lane >> 2, tg = lane & 3;

    unsigned af[8][4];
    {
        int r = w * 16 + (lane & 15);
        int kof = (lane >> 4) * 8;
#pragma unroll
        for (int kt = 0; kt < 8; kt++) {
            unsigned addr = (unsigned)__cvta_generic_to_shared(
                xs + r * XS_STR + kt * 16 + kof);
            asm volatile(
                "ldmatrix.sync.aligned.m8n8.x4.shared.b16 {%0,%1,%2,%3}, [%4];"
                : "=r"(af[kt][0]), "=r"(af[kt][1]), "=r"(af[kt][2]), "=r"(af[kt][3])
                : "r"(addr));
        }
    }

#pragma unroll
    for (int nt = 0; nt < 8; nt++) {
        float c0 = 0.f, c1 = 0.f, c2 = 0.f, c3 = 0.f;
        int brow = nt * 8 + (lane & 7);
        int bk = ((lane >> 3) & 1) * 8;
#pragma unroll
        for (int kt = 0; kt < 8; kt++) {
            unsigned b0, b1;
            unsigned baddr = (unsigned)__cvta_generic_to_shared(
                ws + brow * XS_STR + kt * 16 + bk);
            asm volatile(
                "ldmatrix.sync.aligned.m8n8.x2.shared.b16 {%0,%1}, [%2];"
                : "=r"(b0), "=r"(b1) : "r"(baddr));
            asm volatile(
                "mma.sync.aligned.m16n8k16.row.col.f32.f16.f16.f32 "
                "{%0,%1,%2,%3}, {%4,%5,%6,%7}, {%8,%9}, {%0,%1,%2,%3};"
                : "+f"(c0), "+f"(c1), "+f"(c2), "+f"(c3)
                : "r"(af[kt][0]), "r"(af[kt][1]), "r"(af[kt][2]), "r"(af[kt][3]),
                  "r"(b0), "r"(b1));
        }
        int col = nt * 8 + tg * 2;
        float2 bv = *(const float2*)(bias + col);
        int n0g = nbase + w * 16 + g;
        if (n0g < n)
            *(__half2*)(out + (size_t)n0g * OUTF + col) =
                __floats2half2_rn(c0 + bv.x, c1 + bv.y);
        int n1g = n0g + 8;
        if (n1g < n)
            *(__half2*)(out + (size_t)n1g * OUTF + col) =
                __floats2half2_rn(c2 + bv.x, c3 + bv.y);
    }
}

// ---------------------------------------------------------------------------
// CSR SpMM hop: 8 lanes/node, 8 cols each, unroll-4 edge loop (MLP=4).
// fp16 gather / fp32 accumulate; OUT_HALF selects output precision.
// ---------------------------------------------------------------------------
template <bool OUT_HALF>
__global__ void spmm_csr_kernel(const int* __restrict__ row_ptr,
                                const int2* __restrict__ csr,
                                const __half* __restrict__ hin,
                                void* __restrict__ hout, int n)
{
    int t = blockIdx.x * blockDim.x + threadIdx.x;
    int v = t >> 3;
    if (v >= n) return;
    int q = (threadIdx.x & 7) * 8;   // column offset (halves)

    int beg = __ldg(&row_ptr[v]);
    int end = __ldg(&row_ptr[v + 1]);

    float a[8];
#pragma unroll
    for (int j = 0; j < 8; j++) a[j] = 0.f;

    int i = beg;
    for (; i + 4 <= end; i += 4) {
        int2 e0 = __ldg(&csr[i]);
        int2 e1 = __ldg(&csr[i + 1]);
        int2 e2 = __ldg(&csr[i + 2]);
        int2 e3 = __ldg(&csr[i + 3]);
        uint4 r0 = *(const uint4*)(hin + (size_t)e0.x * OUTF + q);
        uint4 r1 = *(const uint4*)(hin + (size_t)e1.x * OUTF + q);
        uint4 r2 = *(const uint4*)(hin + (size_t)e2.x * OUTF + q);
        uint4 r3 = *(const uint4*)(hin + (size_t)e3.x * OUTF + q);
        float w0 = __int_as_float(e0.y);
        float w1 = __int_as_float(e1.y);
        float w2 = __int_as_float(e2.y);
        float w3 = __int_as_float(e3.y);
        const unsigned* u0 = &r0.x;
        const unsigned* u1 = &r1.x;
        const unsigned* u2 = &r2.x;
        const unsigned* u3 = &r3.x;
#pragma unroll
        for (int j = 0; j < 4; j++) {
            float2 f0 = __half22float2(*(const __half2*)&u0[j]);
            float2 f1 = __half22float2(*(const __half2*)&u1[j]);
            float2 f2 = __half22float2(*(const __half2*)&u2[j]);
            float2 f3 = __half22float2(*(const __half2*)&u3[j]);
            a[2 * j + 0] = fmaf(w0, f0.x, a[2 * j + 0]);
            a[2 * j + 1] = fmaf(w0, f0.y, a[2 * j + 1]);
            a[2 * j + 0] = fmaf(w1, f1.x, a[2 * j + 0]);
            a[2 * j + 1] = fmaf(w1, f1.y, a[2 * j + 1]);
            a[2 * j + 0] = fmaf(w2, f2.x, a[2 * j + 0]);
            a[2 * j + 1] = fmaf(w2, f2.y, a[2 * j + 1]);
            a[2 * j + 0] = fmaf(w3, f3.x, a[2 * j + 0]);
            a[2 * j + 1] = fmaf(w3, f3.y, a[2 * j + 1]);
        }
    }
    for (; i < end; i++) {
        int2 e0 = __ldg(&csr[i]);
        uint4 r0 = *(const uint4*)(hin + (size_t)e0.x * OUTF + q);
        float w0 = __int_as_float(e0.y);
        const unsigned* u0 = &r0.x;
#pragma unroll
        for (int j = 0; j < 4; j++) {
            float2 f0 = __half22float2(*(const __half2*)&u0[j]);
            a[2 * j + 0] = fmaf(w0, f0.x, a[2 * j + 0]);
            a[2 * j + 1] = fmaf(w0, f0.y, a[2 * j + 1]);
        }
    }

    if (OUT_HALF) {
        uint4 o;
        unsigned* ou = &o.x;
#pragma unroll
        for (int j = 0; j < 4; j++) {
            __half2 h = __floats2half2_rn(a[2 * j], a[2 * j + 1]);
            ou[j] = *(const unsigned*)&h;
        }
        *(uint4*)((__half*)hout + (size_t)v * OUTF + q) = o;
    } else {
        float* fo = (float*)hout + (size_t)v * OUTF + q;
        *(float4*)(fo)     = make_float4(a[0], a[1], a[2], a[3]);
        *(float4*)(fo + 4) = make_float4(a[4], a[5], a[6], a[7]);
    }
}

// ---------------------------------------------------------------------------
extern "C" void kernel_launch(void* const* d_in, const int* in_sizes, int n_in,
                              void* d_out, int out_size)
{
    const float* x  = (const float*)d_in[0];
    const int*   ei = (const int*)d_in[1];
    const float* ew = (const float*)d_in[2];
    const float* Ww = (const float*)d_in[3];
    const float* Wb = (const float*)d_in[4];
    float* out = (float*)d_out;

    int n = in_sizes[0] / INF;     // 100000
    int E = in_sizes[2];           // 1600000

    __half *pA, *pB;
    int *pDegState, *pRow, *pW;
    int2 *pCsr;
    cudaGetSymbolAddress((void**)&pA, g_hA);
    cudaGetSymbolAddress((void**)&pB, g_hB);
    cudaGetSymbolAddress((void**)&pDegState, g_degstate);
    cudaGetSymbolAddress((void**)&pRow, g_row_ptr);
    cudaGetSymbolAddress((void**)&pW, g_wptr);
    cudaGetSymbolAddress((void**)&pCsr, g_csr);

    int* pDeg = pDegState;
    unsigned long long* pState = (unsigned long long*)(pDegState + MAX_NODES);

    const int GEMM_SMEM = (128 + 64) * XS_STR * (int)sizeof(__half);  // 52224 B
    cudaFuncSetAttribute(gemm_hmma_kernel,
                         cudaFuncAttributeMaxDynamicSharedMemorySize, GEMM_SMEM);

    int nb = (n + 255) / 256;

    // 1: GEMM (also zeros deg + lookback state in prologue)
    gemm_hmma_kernel<<<(n + 127) / 128, 256, GEMM_SMEM>>>(x, Ww, Wb, pA,
                                                          pDegState, n);
    // 2: degree count
    count_kernel<<<(E + 255) / 256, 256>>>(ei, E, pDeg);
    // 3: exclusive scan (single launch, decoupled lookback)
    scan_lookback_kernel<<<nb, 256>>>(pDeg, pState, pRow, pW, n, E);
    // 4: scatter edges into CSR
    scatter_kernel<<<(E + 255) / 256, 256>>>(ei, ew, pW, pCsr, E);

    // 5-7: propagation hops (hop1 is graph node #5 -> ncu capture slot)
    int hop_blocks = (n * 8 + 255) / 256;
    spmm_csr_kernel<true ><<<hop_blocks, 256>>>(pRow, pCsr, pA, pB, n);
    spmm_csr_kernel<true ><<<hop_blocks, 256>>>(pRow, pCsr, pB, pA, n);
    spmm_csr_kernel<false><<<hop_blocks, 256>>>(pRow, pCsr, pA, out, n);
}